// round 7
// baseline (speedup 1.0000x reference)
#include <cuda_runtime.h>
#include <stdint.h>
#include <math.h>

#define BB 16
#define NTOT 21824
#define TOPN 1000
#define MAXOBJ 100
#define CAND_CAP 4096
#define NBUCKET 16384      // score < 1.0 -> (bits>>16) <= 0x3F7F < 16384
#define MROW 33            // padded mask row stride (words) -> conflict-free diagonal reads

// ---------------- scratch (static device globals; zero-initialized at load) ----------------
__device__ uint32_t d_scoreBits[BB * NTOT];
__device__ int      d_cls[BB * NTOT];
__device__ float4   d_box[BB * NTOT];
__device__ uint32_t d_hist[BB * NBUCKET];          // cleared by k_select after use
__device__ float    d_topS[BB * TOPN];
__device__ int      d_topC[BB * TOPN];
__device__ float4   d_topB[BB * TOPN];
__device__ float    d_area[BB * TOPN];
__device__ uint32_t d_validW[BB * 32];

struct Ptrs {
    const float* cls[5];
    const float* reg[5];
    const float* ctr[5];
    const float* pos[5];
};

__constant__ int c_HW[5]  = {16384, 4096, 1024, 256, 64};

// ---------------- decode: warp per anchor, histogram fused ----------------
__global__ void k_decode(Ptrs p) {
    int warpId = (blockIdx.x * blockDim.x + threadIdx.x) >> 5;
    int lane = threadIdx.x & 31;
    if (warpId >= BB * NTOT) return;
    int b = warpId / NTOT;
    int a = warpId - b * NTOT;

    int lvl, hw;
    if (a < 16384)      { lvl = 0; hw = a; }
    else if (a < 20480) { lvl = 1; hw = a - 16384; }
    else if (a < 21504) { lvl = 2; hw = a - 20480; }
    else if (a < 21760) { lvl = 3; hw = a - 21504; }
    else                { lvl = 4; hw = a - 21760; }

    long base = (long)b * c_HW[lvl] + hw;
    const float* c = p.cls[lvl] + base * 80;

    float v0 = c[lane];
    float v1 = c[lane + 32];
    float v2 = (lane < 16) ? c[lane + 64] : -1.0f;  // all real values >= 0

    float m = v0; int mi = lane;
    if (v1 > m) { m = v1; mi = lane + 32; }
    if (v2 > m) { m = v2; mi = lane + 64; }

    // warp argmax: positive floats -> uint order == float order
    uint32_t mb = __float_as_uint(m);
    uint32_t rmax = __reduce_max_sync(0xffffffffu, mb);
    unsigned cand = (mb == rmax) ? (unsigned)mi : 0x7fffffffu;
    unsigned midx = __reduce_min_sync(0xffffffffu, cand);   // exact first-index tiebreak

    if (lane == 0) {
        float mv = __uint_as_float(rmax);
        float t = p.ctr[lvl][base];
        float px = p.pos[lvl][base * 2 + 0];
        float py = p.pos[lvl][base * 2 + 1];
        const float* r = p.reg[lvl] + base * 4;
        float s = __fsqrt_rn(mv * t);
        float4 bx;
        bx.x = truncf(px - r[0]);
        bx.y = truncf(py - r[1]);
        bx.z = truncf(px + r[2]);
        bx.w = truncf(py + r[3]);
        uint32_t bits = __float_as_uint(s);
        d_scoreBits[warpId] = bits;
        d_cls[warpId] = (int)midx;
        d_box[warpId] = bx;
        uint32_t bk = bits >> 16;
        if (bk >= NBUCKET) bk = NBUCKET - 1;
        atomicAdd(&d_hist[b * NBUCKET + bk], 1u);
    }
}

// ---------------- per-batch: pivot + collect + sort + emit top-1000 ----------------
__global__ void __launch_bounds__(1024, 1) k_select() {
    __shared__ unsigned long long sk[CAND_CAP];
    __shared__ uint32_t sA[1024], sB[1024];
    __shared__ uint32_t svalid[32];
    __shared__ uint32_t shCnt;
    __shared__ uint32_t shPivot;
    __shared__ int shChunk;

    int b = blockIdx.x;
    int t = threadIdx.x;   // 1024
    uint32_t* h = &d_hist[b * NBUCKET];

    #pragma unroll
    for (int i = t; i < CAND_CAP; i += 1024) sk[i] = 0ULL;
    if (t == 0) shCnt = 0u;
    if (t < 32) svalid[t] = 0u;

    // chunk sums: thread t owns buckets [t*16, t*16+16)
    {
        uint32_t s = 0;
        const uint4* hv = (const uint4*)(h + t * 16);
        #pragma unroll
        for (int q = 0; q < 4; q++) {
            uint4 v = hv[q];
            s += v.x + v.y + v.z + v.w;
        }
        sA[t] = s;
    }
    __syncthreads();

    // parallel inclusive suffix scan over 1024 chunk sums (Hillis-Steele, ping-pong)
    uint32_t* src = sA; uint32_t* dst = sB;
    #pragma unroll
    for (int off = 1; off < 1024; off <<= 1) {
        uint32_t v = src[t] + ((t + off < 1024) ? src[t + off] : 0u);
        dst[t] = v;
        __syncthreads();
        uint32_t* tmp = src; src = dst; dst = tmp;
    }

    if (src[t] >= TOPN && (t == 1023 || src[t + 1] < TOPN)) shChunk = t;
    __syncthreads();
    if (t == 0) {
        int c = shChunk;
        uint32_t run = (c < 1023) ? src[c + 1] : 0u;
        uint32_t piv = (uint32_t)(c * 16);
        for (int v = c * 16 + 15; v >= c * 16; v--) {
            run += h[v];
            if (run >= TOPN) { piv = (uint32_t)v; break; }
        }
        shPivot = piv;
    }
    __syncthreads();
    uint32_t pivot = shPivot;

    // zero hist slice for next replay
    {
        uint4 z = make_uint4(0u, 0u, 0u, 0u);
        ((uint4*)(h + t * 16))[0] = z;
        ((uint4*)(h + t * 16))[1] = z;
        ((uint4*)(h + t * 16))[2] = z;
        ((uint4*)(h + t * 16))[3] = z;
    }

    // collect candidates >= pivot into shared
    const uint32_t* sbits = &d_scoreBits[b * NTOT];
    for (int i = t; i < NTOT; i += 1024) {
        uint32_t bits = sbits[i];
        if ((bits >> 16) >= pivot) {
            uint32_t slot = atomicAdd(&shCnt, 1u);
            if (slot < CAND_CAP)
                sk[slot] = ((unsigned long long)bits << 15) |
                           (unsigned long long)(32767 - i);
        }
    }
    __syncthreads();

    uint32_t cnt = shCnt;
    if (cnt > CAND_CAP) cnt = CAND_CAP;
    int sortN = 1024;
    while (sortN < (int)cnt) sortN <<= 1;

    // bitonic sort, descending
    for (int k = 2; k <= sortN; k <<= 1) {
        for (int j = k >> 1; j > 0; j >>= 1) {
            for (int i = t; i < sortN; i += 1024) {
                int ix = i ^ j;
                if (ix > i) {
                    bool dir = ((i & k) == 0);
                    unsigned long long A = sk[i], Bv = sk[ix];
                    if ((A < Bv) == dir) { sk[i] = Bv; sk[ix] = A; }
                }
            }
            __syncthreads();
        }
    }

    // emit top-1000
    if (t < TOPN) {
        unsigned long long key = sk[t];
        float s; int c; float4 bx;
        int a = 32767 - (int)(key & 0x7FFFULL);
        if (key == 0ULL || a < 0 || a >= NTOT) {
            s = -1e30f; c = 0; bx = make_float4(0.f, 0.f, 0.f, 0.f);
        } else {
            s = __uint_as_float((uint32_t)(key >> 15));
            int g = b * NTOT + a;
            c = d_cls[g];
            bx = d_box[g];
        }
        d_topS[b * TOPN + t] = s;
        d_topC[b * TOPN + t] = c;
        d_topB[b * TOPN + t] = bx;
        float w = bx.z - bx.x, hh = bx.w - bx.y;
        d_area[b * TOPN + t] = fmaxf(w * hh, 1e-4f);
        if (s > 0.05f) atomicOr(&svalid[t >> 5], 1u << (t & 31));
    }
    __syncthreads();
    if (t < 32) d_validW[b * 32 + t] = svalid[t];
}

// ---------------- FUSED mask + serial NMS: grid B, 1024 threads ----------------
// Dynamic SMEM layout: float4 sb[TOPN] | float sa[TOPN] | uint32 mask[TOPN*MROW]
__global__ void __launch_bounds__(1024, 1) k_masknms(float* out) {
    extern __shared__ uint32_t dyn[];
    float4*   sb = (float4*)dyn;                        // 16000 B
    float*    sa = (float*)(dyn + TOPN * 4);            // 4000 B
    uint32_t* sm = dyn + TOPN * 5;                      // TOPN*MROW words
    __shared__ uint32_t sv[32];
    __shared__ uint32_t srnz[32];

    int b = blockIdx.x;
    int t = threadIdx.x;
    int lane = t & 31, w = t >> 5;

    // load boxes/areas, zero mask, init outputs
    for (int i = t; i < TOPN; i += 1024) {
        sb[i] = d_topB[b * TOPN + i];
        sa[i] = d_area[b * TOPN + i];
    }
    {
        uint4* mz = (uint4*)sm;
        const int NZ = TOPN * MROW / 4;   // 8250
        #pragma unroll 4
        for (int i = t; i < NZ; i += 1024) mz[i] = make_uint4(0u, 0u, 0u, 0u);
        sm[TOPN * MROW - 2] = 0u;         // remainder words (33000 % 4 == 0, safe anyway)
    }
    if (t < 32) { sv[t] = d_validW[b * 32 + t]; srnz[t] = 0u; }
    for (int k = t; k < 100; k += 1024) {
        out[b * 100 + k] = -1.0f;
        out[1600 + b * 100 + k] = -1.0f;
    }
    for (int k = t; k < 400; k += 1024)
        out[3200 + b * 400 + k] = 0.0f;
    __syncthreads();

    // ---- mask compute: warp w handles rows w, w+32, ... ----
    for (int i = w; i < TOPN; i += 32) {
        bool vi = (sv[i >> 5] >> (i & 31)) & 1u;
        if (!vi) continue;                // row stays all-zero
        float4 bi = sb[i];
        float ai = sa[i];
        uint32_t anyrow = 0u;
        int jw0 = i >> 5;
        for (int jw = jw0; jw < 32; jw++) {
            int j = jw * 32 + lane;
            bool pred = false;
            if (j < TOPN && j > i) {
                float tlx = fmaxf(bi.x, sb[j].x), tly = fmaxf(bi.y, sb[j].y);
                float brx = fminf(bi.z, sb[j].z), bry = fminf(bi.w, sb[j].w);
                float ow = fmaxf(brx - tlx, 0.f), oh = fmaxf(bry - tly, 0.f);
                float inter = ow * oh;
                float uni = fmaxf(ai + sa[j] - inter, 1e-4f);
                pred = (inter / uni) >= 0.6f;
            }
            uint32_t m = __ballot_sync(0xffffffffu, pred);
            anyrow |= m;
            if (lane == 0) sm[i * MROW + jw] = m;
        }
        if (lane == 0 && anyrow)
            atomicOr(&srnz[i >> 5], 1u << (i & 31));
    }
    __syncthreads();

    if (t >= 32) return;   // warp 0 only from here

    uint32_t rnzAll = srnz[lane];

    // diagonal prefetch: dwreg[bw] = row (bw*32+lane)'s word bw
    // addr = (bw*32+lane)*MROW + bw ; lane stride = MROW=33 -> conflict-free
    uint32_t dwreg[32];
    #pragma unroll
    for (int bw = 0; bw < 32; bw++) {
        int row = bw * 32 + lane;
        dwreg[bw] = (row < TOPN) ? sm[row * MROW + bw] : 0u;
    }

    uint32_t supp = 0;
    for (int bw = 0; bw < 32; bw++) {
        uint32_t sw = __shfl_sync(0xffffffffu, supp, bw);
        uint32_t dw = dwreg[bw];
        uint32_t conflict = __ballot_sync(0xffffffffu, dw != 0u) & ~sw;
        uint32_t active;
        if (!conflict) {
            active = ~sw;
        } else {
            active = ~sw;
            uint32_t rem = conflict;
            while (rem) {
                int hrow = __ffs(rem) - 1;
                rem &= rem - 1;
                uint32_t dwh = __shfl_sync(0xffffffffu, dw, hrow);
                if ((active >> hrow) & 1u) {
                    active &= ~dwh;
                    rem &= ~dwh;
                }
            }
        }
        if (bw == 31) active &= 0xFFu;
        uint32_t rz = __shfl_sync(0xffffffffu, rnzAll, bw);
        uint32_t need = active & rz;
        while (need) {
            int r0 = __ffs(need) - 1;
            need &= need - 1;
            uint32_t v = sm[(bw * 32 + r0) * MROW + lane];
            if (need) {
                int r1 = __ffs(need) - 1;
                need &= need - 1;
                v |= sm[(bw * 32 + r1) * MROW + lane];
            }
            supp |= v;
        }
    }

    uint32_t kw = sv[lane] & ~supp;

    // exclusive scan of keep-counts across lanes
    int pc = __popc(kw);
    int pre = pc;
    #pragma unroll
    for (int off = 1; off < 32; off <<= 1) {
        int n = __shfl_up_sync(0xffffffffu, pre, off);
        if (lane >= off) pre += n;
    }
    int r = pre - pc;

    uint32_t wv = kw;
    while (wv) {
        int bit = __ffs(wv) - 1;
        wv &= wv - 1;
        if (r < MAXOBJ) {
            int i = lane * 32 + bit;
            out[b * 100 + r] = d_topS[b * TOPN + i];
            out[1600 + b * 100 + r] = (float)d_topC[b * TOPN + i];
            float4 bx = d_topB[b * TOPN + i];
            float* ob = out + 3200 + (b * 100 + r) * 4;
            ob[0] = bx.x; ob[1] = bx.y; ob[2] = bx.z; ob[3] = bx.w;
        }
        r++;
    }
}

// ---------------- host launch ----------------
extern "C" void kernel_launch(void* const* d_in, const int* in_sizes, int n_in,
                              void* d_out, int out_size) {
    (void)n_in; (void)out_size;
    const int HW0 = 16384;
    Ptrs P;
    bool dictOrder = (in_sizes[1] == BB * HW0 * 4);  // reg0 right after cls0?
    if (dictOrder) {
        for (int l = 0; l < 5; l++) {
            P.cls[l] = (const float*)d_in[l * 4 + 0];
            P.reg[l] = (const float*)d_in[l * 4 + 1];
            P.ctr[l] = (const float*)d_in[l * 4 + 2];
            P.pos[l] = (const float*)d_in[l * 4 + 3];
        }
    } else {
        for (int l = 0; l < 5; l++) {
            P.cls[l] = (const float*)d_in[l];
            P.reg[l] = (const float*)d_in[5 + l];
            P.ctr[l] = (const float*)d_in[10 + l];
            P.pos[l] = (const float*)d_in[15 + l];
        }
    }

    float* out = (float*)d_out;

    // dynamic smem: sb (16000) + sa (4000) + mask (TOPN*MROW*4 = 132000) = 152000 B
    static const size_t FUSED_SHM = (size_t)(TOPN * 5 + TOPN * MROW) * sizeof(uint32_t);
    cudaFuncSetAttribute(k_masknms, cudaFuncAttributeMaxDynamicSharedMemorySize,
                         (int)FUSED_SHM);

    int warps = BB * NTOT;
    k_decode<<<(warps * 32 + 255) / 256, 256>>>(P);
    k_select<<<BB, 1024>>>();
    k_masknms<<<BB, 1024, FUSED_SHM>>>(out);
}

// round 8
// speedup vs baseline: 2.1415x; 2.1415x over previous
#include <cuda_runtime.h>
#include <stdint.h>
#include <math.h>

#define BB 16
#define NTOT 21824
#define TOPN 1000
#define MAXOBJ 100
#define CAND_CAP 4096
#define NBUCKET 16384      // score < 1.0 -> (bits>>16) <= 0x3F7F < 16384

// ---------------- scratch (static device globals; zero-initialized at load) ----------------
__device__ uint32_t d_scoreBits[BB * NTOT];
__device__ int      d_cls[BB * NTOT];
__device__ float4   d_box[BB * NTOT];
__device__ uint32_t d_hist[BB * NBUCKET];          // cleared by k_select after use
__device__ float    d_topS[BB * TOPN];
__device__ int      d_topC[BB * TOPN];
__device__ float4   d_topB[BB * TOPN];
__device__ float    d_area[BB * TOPN];
__device__ uint32_t d_validW[BB * 32];
__device__ uint32_t d_mask[BB * TOPN * 32];        // zero rows are never written (stay 0)
__device__ uint32_t d_rnz[BB * 32];                // row-has-nonzero-mask bitmap

struct Ptrs {
    const float* cls[5];
    const float* reg[5];
    const float* ctr[5];
    const float* pos[5];
};

__constant__ int c_HW[5]  = {16384, 4096, 1024, 256, 64};

// ---------------- decode: warp per anchor, epilogue loads prefetched ----------------
__global__ void k_decode(Ptrs p) {
    int warpId = (blockIdx.x * blockDim.x + threadIdx.x) >> 5;
    int lane = threadIdx.x & 31;
    if (warpId >= BB * NTOT) return;
    int b = warpId / NTOT;
    int a = warpId - b * NTOT;

    int lvl, hw;
    if (a < 16384)      { lvl = 0; hw = a; }
    else if (a < 20480) { lvl = 1; hw = a - 16384; }
    else if (a < 21504) { lvl = 2; hw = a - 20480; }
    else if (a < 21760) { lvl = 3; hw = a - 21504; }
    else                { lvl = 4; hw = a - 21760; }

    long base = (long)b * c_HW[lvl] + hw;
    const float* c = p.cls[lvl] + base * 80;

    // prefetch epilogue scalars on side lanes, overlapping the class loads:
    //   lane 0 -> ctr ; lane 1 -> pos (float2) ; lane 2 -> reg (float4)
    float  sc_t = 0.f;
    float2 sc_p = make_float2(0.f, 0.f);
    float4 sc_r = make_float4(0.f, 0.f, 0.f, 0.f);
    if (lane == 0) sc_t = p.ctr[lvl][base];
    if (lane == 1) sc_p = ((const float2*)p.pos[lvl])[base];
    if (lane == 2) sc_r = ((const float4*)p.reg[lvl])[base];

    float v0 = c[lane];
    float v1 = c[lane + 32];
    float v2 = (lane < 16) ? c[lane + 64] : -1.0f;  // all real values >= 0

    float m = v0; int mi = lane;
    if (v1 > m) { m = v1; mi = lane + 32; }
    if (v2 > m) { m = v2; mi = lane + 64; }

    // warp argmax: positive floats -> uint order == float order
    uint32_t mb = __float_as_uint(m);
    uint32_t rmax = __reduce_max_sync(0xffffffffu, mb);
    unsigned cand = (mb == rmax) ? (unsigned)mi : 0x7fffffffu;
    unsigned midx = __reduce_min_sync(0xffffffffu, cand);   // exact first-index tiebreak

    // bring prefetched scalars to lane 0
    float px = __shfl_sync(0xffffffffu, sc_p.x, 1);
    float py = __shfl_sync(0xffffffffu, sc_p.y, 1);
    float r0 = __shfl_sync(0xffffffffu, sc_r.x, 2);
    float r1 = __shfl_sync(0xffffffffu, sc_r.y, 2);
    float r2 = __shfl_sync(0xffffffffu, sc_r.z, 2);
    float r3 = __shfl_sync(0xffffffffu, sc_r.w, 2);

    if (lane == 0) {
        float mv = __uint_as_float(rmax);
        float s = __fsqrt_rn(mv * sc_t);
        float4 bx;
        bx.x = truncf(px - r0);
        bx.y = truncf(py - r1);
        bx.z = truncf(px + r2);
        bx.w = truncf(py + r3);
        uint32_t bits = __float_as_uint(s);
        d_scoreBits[warpId] = bits;
        d_cls[warpId] = (int)midx;
        d_box[warpId] = bx;
        uint32_t bk = bits >> 16;
        if (bk >= NBUCKET) bk = NBUCKET - 1;
        atomicAdd(&d_hist[b * NBUCKET + bk], 1u);
    }
}

// ---------------- per-batch: pivot + collect + sort + emit top-1000 ----------------
__global__ void __launch_bounds__(1024, 1) k_select() {
    __shared__ unsigned long long sk[CAND_CAP];
    __shared__ uint32_t sA[1024], sB[1024];
    __shared__ uint32_t svalid[32];
    __shared__ uint32_t shCnt;
    __shared__ uint32_t shPivot;
    __shared__ int shChunk;

    int b = blockIdx.x;
    int t = threadIdx.x;   // 1024
    uint32_t* h = &d_hist[b * NBUCKET];

    #pragma unroll
    for (int i = t; i < CAND_CAP; i += 1024) sk[i] = 0ULL;
    if (t == 0) shCnt = 0u;
    if (t < 32) { svalid[t] = 0u; d_rnz[b * 32 + t] = 0u; }

    // chunk sums: thread t owns buckets [t*16, t*16+16)
    {
        uint32_t s = 0;
        const uint4* hv = (const uint4*)(h + t * 16);
        #pragma unroll
        for (int q = 0; q < 4; q++) {
            uint4 v = hv[q];
            s += v.x + v.y + v.z + v.w;
        }
        sA[t] = s;
    }
    __syncthreads();

    // parallel inclusive suffix scan over 1024 chunk sums (Hillis-Steele, ping-pong)
    uint32_t* src = sA; uint32_t* dst = sB;
    #pragma unroll
    for (int off = 1; off < 1024; off <<= 1) {
        uint32_t v = src[t] + ((t + off < 1024) ? src[t + off] : 0u);
        dst[t] = v;
        __syncthreads();
        uint32_t* tmp = src; src = dst; dst = tmp;
    }

    if (src[t] >= TOPN && (t == 1023 || src[t + 1] < TOPN)) shChunk = t;
    __syncthreads();
    if (t == 0) {
        int c = shChunk;
        uint32_t run = (c < 1023) ? src[c + 1] : 0u;
        uint32_t piv = (uint32_t)(c * 16);
        for (int v = c * 16 + 15; v >= c * 16; v--) {
            run += h[v];
            if (run >= TOPN) { piv = (uint32_t)v; break; }
        }
        shPivot = piv;
    }
    __syncthreads();
    uint32_t pivot = shPivot;

    // zero hist slice for next replay
    {
        uint4 z = make_uint4(0u, 0u, 0u, 0u);
        ((uint4*)(h + t * 16))[0] = z;
        ((uint4*)(h + t * 16))[1] = z;
        ((uint4*)(h + t * 16))[2] = z;
        ((uint4*)(h + t * 16))[3] = z;
    }

    // collect candidates >= pivot into shared
    const uint32_t* sbits = &d_scoreBits[b * NTOT];
    for (int i = t; i < NTOT; i += 1024) {
        uint32_t bits = sbits[i];
        if ((bits >> 16) >= pivot) {
            uint32_t slot = atomicAdd(&shCnt, 1u);
            if (slot < CAND_CAP)
                sk[slot] = ((unsigned long long)bits << 15) |
                           (unsigned long long)(32767 - i);
        }
    }
    __syncthreads();

    uint32_t cnt = shCnt;
    if (cnt > CAND_CAP) cnt = CAND_CAP;
    int sortN = 1024;
    while (sortN < (int)cnt) sortN <<= 1;

    // bitonic sort, descending
    for (int k = 2; k <= sortN; k <<= 1) {
        for (int j = k >> 1; j > 0; j >>= 1) {
            for (int i = t; i < sortN; i += 1024) {
                int ix = i ^ j;
                if (ix > i) {
                    bool dir = ((i & k) == 0);
                    unsigned long long A = sk[i], Bv = sk[ix];
                    if ((A < Bv) == dir) { sk[i] = Bv; sk[ix] = A; }
                }
            }
            __syncthreads();
        }
    }

    // emit top-1000
    if (t < TOPN) {
        unsigned long long key = sk[t];
        float s; int c; float4 bx;
        int a = 32767 - (int)(key & 0x7FFFULL);
        if (key == 0ULL || a < 0 || a >= NTOT) {
            s = -1e30f; c = 0; bx = make_float4(0.f, 0.f, 0.f, 0.f);
        } else {
            s = __uint_as_float((uint32_t)(key >> 15));
            int g = b * NTOT + a;
            c = d_cls[g];
            bx = d_box[g];
        }
        d_topS[b * TOPN + t] = s;
        d_topC[b * TOPN + t] = c;
        d_topB[b * TOPN + t] = bx;
        float w = bx.z - bx.x, hh = bx.w - bx.y;
        d_area[b * TOPN + t] = fmaxf(w * hh, 1e-4f);
        if (s > 0.05f) atomicOr(&svalid[t >> 5], 1u << (t & 31));
    }
    __syncthreads();
    if (t < 32) d_validW[b * 32 + t] = svalid[t];
}

// ---------------- IoU mask matrix: grid (B, 16), 1024 threads ----------------
__global__ void __launch_bounds__(1024, 1) k_mask() {
    __shared__ float4 sb[TOPN];
    __shared__ float  sa[TOPN];
    __shared__ uint32_t sv[32];
    int b = blockIdx.x;
    int rb = blockIdx.y;
    int t = threadIdx.x;
    for (int i = t; i < TOPN; i += 1024) {
        sb[i] = d_topB[b * TOPN + i];
        sa[i] = d_area[b * TOPN + i];
    }
    if (t < 32) sv[t] = d_validW[b * 32 + t];
    __syncthreads();

    int lane = t & 31, w = t >> 5;
    int rbase = rb * 63;
    int rend = rbase + 63; if (rend > TOPN) rend = TOPN;
    for (int i = rbase + w; i < rend; i += 32) {
        bool vi = (sv[i >> 5] >> (i & 31)) & 1u;
        if (!vi) continue;   // whole row is zero; never written, stays 0
        float4 bi = sb[i];
        float ai = sa[i];
        uint32_t anyrow = 0u;
        int jw0 = i >> 5;
        #pragma unroll 4
        for (int jw = jw0; jw < 32; jw++) {
            int j = jw * 32 + lane;
            bool pred = false;
            if (j < TOPN && j > i) {
                float tlx = fmaxf(bi.x, sb[j].x), tly = fmaxf(bi.y, sb[j].y);
                float brx = fminf(bi.z, sb[j].z), bry = fminf(bi.w, sb[j].w);
                float ow = fmaxf(brx - tlx, 0.f), oh = fmaxf(bry - tly, 0.f);
                float inter = ow * oh;
                float uni = fmaxf(ai + sa[j] - inter, 1e-4f);
                pred = (inter / uni) >= 0.6f;
            }
            uint32_t m = __ballot_sync(0xffffffffu, pred);
            anyrow |= m;
            if (lane == 0) d_mask[(b * TOPN + i) * 32 + jw] = m;
        }
        if (lane == 0 && anyrow)
            atomicOr(&d_rnz[b * 32 + (i >> 5)], 1u << (i & 31));
    }
}

// ---------------- serial suppression + output scatter: grid B, 512 threads ----------------
__global__ void __launch_bounds__(512, 1) k_nms(float* out) {
    extern __shared__ uint32_t shm[];   // TOPN*32 words = 125 KB
    int b = blockIdx.x;
    int t = threadIdx.x;
    int lane = t & 31;

    // stage mask into shared: vectorized uint4, unrolled for MLP (L2-resident data)
    {
        uint4* shv = (uint4*)shm;
        const uint4* gm = (const uint4*)&d_mask[b * TOPN * 32];
        #pragma unroll 4
        for (int i = t; i < TOPN * 8; i += 512)
            shv[i] = gm[i];
    }

    // init outputs for this batch
    for (int k = t; k < 100; k += 512) {
        out[b * 100 + k] = -1.0f;               // scores
        out[1600 + b * 100 + k] = -1.0f;        // classes
    }
    for (int k = t; k < 400; k += 512)
        out[3200 + b * 400 + k] = 0.0f;         // boxes
    __syncthreads();

    if (t >= 32) return;  // warp 0 only from here

    // prefetch intra-block diagonal words: dwreg[bw] = my row's word bw
    uint32_t dwreg[32];
    #pragma unroll
    for (int bw = 0; bw < 32; bw++) {
        int row = bw * 32 + lane;
        dwreg[bw] = (row < TOPN) ? shm[row * 32 + bw] : 0u;
    }
    uint32_t rnzAll = d_rnz[b * 32 + lane];   // bitmap word `lane`

    uint32_t supp = 0;
    for (int bw = 0; bw < 32; bw++) {
        uint32_t sw = __shfl_sync(0xffffffffu, supp, bw);  // supp word for this block
        uint32_t dw = dwreg[bw];
        uint32_t conflict = __ballot_sync(0xffffffffu, dw != 0u) & ~sw;
        uint32_t active;
        if (!conflict) {
            active = ~sw;
        } else {
            active = ~sw;
            uint32_t rem = conflict;
            while (rem) {
                int hrow = __ffs(rem) - 1;
                rem &= rem - 1;
                uint32_t dwh = __shfl_sync(0xffffffffu, dw, hrow);
                if ((active >> hrow) & 1u) {
                    active &= ~dwh;   // suppress its targets (all > hrow)
                    rem &= ~dwh;      // suppressed hazards can't suppress
                }
            }
        }
        if (bw == 31) active &= 0xFFu;   // rows >= 1000 don't exist
        uint32_t rz = __shfl_sync(0xffffffffu, rnzAll, bw);
        uint32_t need = active & rz;     // active rows with nonzero mask rows
        while (need) {
            int r0 = __ffs(need) - 1;
            need &= need - 1;
            uint32_t v = shm[(bw * 32 + r0) * 32 + lane];
            if (need) {
                int r1 = __ffs(need) - 1;
                need &= need - 1;
                v |= shm[(bw * 32 + r1) * 32 + lane];
            }
            supp |= v;
        }
    }

    uint32_t kw = d_validW[b * 32 + lane] & ~supp;

    // exclusive scan of keep-counts across lanes
    int pc = __popc(kw);
    int pre = pc;
    #pragma unroll
    for (int off = 1; off < 32; off <<= 1) {
        int n = __shfl_up_sync(0xffffffffu, pre, off);
        if (lane >= off) pre += n;
    }
    int r = pre - pc;

    uint32_t wv = kw;
    while (wv) {
        int bit = __ffs(wv) - 1;
        wv &= wv - 1;
        if (r < MAXOBJ) {
            int i = lane * 32 + bit;
            out[b * 100 + r] = d_topS[b * TOPN + i];
            out[1600 + b * 100 + r] = (float)d_topC[b * TOPN + i];
            float4 bx = d_topB[b * TOPN + i];
            float* ob = out + 3200 + (b * 100 + r) * 4;
            ob[0] = bx.x; ob[1] = bx.y; ob[2] = bx.z; ob[3] = bx.w;
        }
        r++;
    }
}

// ---------------- host launch ----------------
extern "C" void kernel_launch(void* const* d_in, const int* in_sizes, int n_in,
                              void* d_out, int out_size) {
    (void)n_in; (void)out_size;
    const int HW0 = 16384;
    Ptrs P;
    bool dictOrder = (in_sizes[1] == BB * HW0 * 4);  // reg0 right after cls0?
    if (dictOrder) {
        for (int l = 0; l < 5; l++) {
            P.cls[l] = (const float*)d_in[l * 4 + 0];
            P.reg[l] = (const float*)d_in[l * 4 + 1];
            P.ctr[l] = (const float*)d_in[l * 4 + 2];
            P.pos[l] = (const float*)d_in[l * 4 + 3];
        }
    } else {
        for (int l = 0; l < 5; l++) {
            P.cls[l] = (const float*)d_in[l];
            P.reg[l] = (const float*)d_in[5 + l];
            P.ctr[l] = (const float*)d_in[10 + l];
            P.pos[l] = (const float*)d_in[15 + l];
        }
    }

    float* out = (float*)d_out;

    static const size_t NMS_SHM = (size_t)TOPN * 32 * sizeof(uint32_t);
    cudaFuncSetAttribute(k_nms, cudaFuncAttributeMaxDynamicSharedMemorySize,
                         (int)NMS_SHM);

    int warps = BB * NTOT;
    k_decode<<<(warps * 32 + 255) / 256, 256>>>(P);
    k_select<<<BB, 1024>>>();
    dim3 mg(BB, 16);
    k_mask<<<mg, 1024>>>();
    k_nms<<<BB, 512, NMS_SHM>>>(out);
}